// round 17
// baseline (speedup 1.0000x reference)
#include <cuda_runtime.h>
#include <cuda_fp16.h>
#include <stdint.h>

#define DM   768
#define NH   12
#define DKH  64
#define NB   2
#define SL   4096
#define MT   (NB * SL)
#define NBH  (NB * NH)

// fp16 operand scratch (allocation-free)
__device__ __align__(16) __half g_X [(size_t)MT * DM];
__device__ __align__(16) __half g_W [(size_t)4 * DM * DM];    // Wq,Wk,Wv,Wo
__device__ __align__(16) __half g_Q [(size_t)NBH * SL * DKH];
__device__ __align__(16) __half g_K [(size_t)NBH * SL * DKH];
__device__ __align__(16) __half g_Vt[(size_t)NBH * DKH * SL]; // [bh, d, L]
__device__ __align__(16) __half g_O [(size_t)MT * DM];

// ---------------- helpers ----------------
__device__ __forceinline__ uint32_t smem_u32(const void* p) {
    uint32_t a;
    asm("{ .reg .u64 t; cvta.to.shared.u64 t, %1; cvt.u32.u64 %0, t; }" : "=r"(a) : "l"(p));
    return a;
}
__device__ __forceinline__ void cpa16(uint32_t dst, const void* src) {
    asm volatile("cp.async.cg.shared.global [%0], [%1], 16;" :: "r"(dst), "l"(src));
}
#define CPA_COMMIT() asm volatile("cp.async.commit_group;" ::: "memory")
#define CPA_WAIT0()  asm volatile("cp.async.wait_group 0;" ::: "memory")

__device__ __forceinline__ float ex2f(float x) {
    float y; asm("ex2.approx.f32 %0, %1;" : "=f"(y) : "f"(x)); return y;
}
__device__ __forceinline__ uint32_t pack_h2(float x, float y) {
    half2 h = __floats2half2_rn(x, y);
    return *(uint32_t*)&h;
}
__device__ __forceinline__ void ldsm4(uint32_t r[4], uint32_t addr) {
    asm volatile("ldmatrix.sync.aligned.m8n8.x4.shared.b16 {%0,%1,%2,%3}, [%4];"
                 : "=r"(r[0]), "=r"(r[1]), "=r"(r[2]), "=r"(r[3]) : "r"(addr));
}

__device__ __forceinline__ void mma16816h(float d[4], const uint32_t a[4],
                                          uint32_t b0, uint32_t b1) {
    asm volatile(
        "mma.sync.aligned.m16n8k16.row.col.f32.f16.f16.f32 "
        "{%0,%1,%2,%3}, {%4,%5,%6,%7}, {%8,%9}, {%0,%1,%2,%3};"
        : "+f"(d[0]), "+f"(d[1]), "+f"(d[2]), "+f"(d[3])
        : "r"(a[0]), "r"(a[1]), "r"(a[2]), "r"(a[3]), "r"(b0), "r"(b1));
}

#define QSCALE 0.18033688011112042f   // (1/8) * log2(e)
#define GEMM_SMEM 32768
#define ATT_SMEM  81920

// ---------------------------------------------------------------------------
// Prepass: X and W -> single fp16.
// ---------------------------------------------------------------------------
__global__ __launch_bounds__(256)
void split_kernel(const float* __restrict__ X,
                  const float* __restrict__ Wq, const float* __restrict__ Wk,
                  const float* __restrict__ Wv, const float* __restrict__ Wo)
{
    const int z = blockIdx.y;
    const float* src;
    uint32_t* dst;
    size_t n;
    if (z == 0) { src = X; dst = (uint32_t*)g_X; n = (size_t)MT * DM; }
    else        { src = (z == 1) ? Wq : (z == 2) ? Wk : (z == 3) ? Wv : Wo;
                  dst = (uint32_t*)(g_W + (size_t)(z - 1) * DM * DM);
                  n = (size_t)DM * DM; }
    size_t npair = n >> 1;
    for (size_t i = (size_t)blockIdx.x * blockDim.x + threadIdx.x;
         i < npair; i += (size_t)gridDim.x * blockDim.x) {
        float2 v = ((const float2*)src)[i];
        dst[i] = pack_h2(v.x, v.y);
    }
}

// ---------------------------------------------------------------------------
// fp16 tensor-core GEMM mainloop, ldmatrix, batched loads, 2 CTAs/SM.
// CTA 128m x 128n, 8 warps (32m x 64n each), K in 32-wide chunks, 2 stages.
// ---------------------------------------------------------------------------
#define GEMM_MAINLOOP(APTR, BPTR)                                                  \
    extern __shared__ __align__(16) char sm_[];                                    \
    const int tid  = threadIdx.x;                                                  \
    const int wid  = tid >> 5;                                                     \
    const int lane = tid & 31;                                                     \
    const int row0 = blockIdx.y * 128;                                             \
    const int col0 = blockIdx.x * 128;                                             \
    const int m0   = (wid & 3) * 32;                                               \
    const int n0   = (wid >> 2) * 64;                                              \
    const int nrow = lane >> 2;                                                    \
    const int r8   = lane & 7;                                                     \
    const int lg   = lane >> 3;                                                    \
    float c[2][8][4];                                                              \
    _Pragma("unroll")                                                              \
    for (int t = 0; t < 2; t++)                                                    \
        _Pragma("unroll")                                                          \
        for (int j = 0; j < 8; j++)                                                \
            _Pragma("unroll")                                                      \
            for (int e = 0; e < 4; e++) c[t][j][e] = 0.f;                          \
    const int lr2 = tid >> 1;                                                      \
    const int cb2 = (tid & 1) * 2;                                                 \
    const __half* gA = (APTR) + (size_t)(row0 + lr2) * DM;                         \
    const __half* gB = (BPTR) + (size_t)(col0 + lr2) * DM;                         \
    const uint32_t sbase = smem_u32(sm_);                                          \
    const uint32_t strow = (uint32_t)(lr2 * 64);                                   \
    const int swz = (lr2 >> 1) & 3;                                                \
    auto issue_chunk = [&](int k0, int stg) {                                      \
        uint32_t sb = sbase + (uint32_t)stg * 16384u;                              \
        _Pragma("unroll")                                                          \
        for (int i = 0; i < 2; i++) {                                              \
            int ch = cb2 + i;                                                      \
            uint32_t d = strow + (uint32_t)((ch ^ swz) * 16);                      \
            cpa16(sb + d,         gA + k0 + ch * 8);                               \
            cpa16(sb + 8192 + d,  gB + k0 + ch * 8);                               \
        }                                                                          \
        CPA_COMMIT();                                                              \
    };                                                                             \
    const int arow_l = (lg & 1) * 8 + r8;                                          \
    const int akh_l  = lg >> 1;                                                    \
    const int brow_l = (lg >> 1) * 8 + r8;                                         \
    const int bkh_l  = lg & 1;                                                     \
    auto lmoff = [&](int r, int chk) -> uint32_t {                                 \
        return (uint32_t)(r * 64 + ((chk ^ ((r >> 1) & 3)) * 16));                 \
    };                                                                             \
    issue_chunk(0, 0);                                                             \
    for (int k0 = 0, ci = 0; k0 < DM; k0 += 32, ci++) {                            \
        CPA_WAIT0();                                                               \
        __syncthreads();                                                           \
        if (k0 + 32 < DM) issue_chunk(k0 + 32, (ci + 1) & 1);                      \
        uint32_t sb = sbase + (uint32_t)(ci & 1) * 16384u;                         \
        _Pragma("unroll")                                                          \
        for (int s = 0; s < 2; s++) {                                              \
            uint32_t af[2][4];                                                     \
            _Pragma("unroll")                                                      \
            for (int t = 0; t < 2; t++)                                            \
                ldsm4(af[t], sb + lmoff(m0 + t * 16 + arow_l, 2 * s + akh_l));     \
            _Pragma("unroll")                                                      \
            for (int jpp = 0; jpp < 2; jpp++) {                                    \
                uint32_t bf2[2][4];                                                \
                _Pragma("unroll")                                                  \
                for (int u = 0; u < 2; u++)                                        \
                    ldsm4(bf2[u], sb + 8192u +                                     \
                          lmoff(n0 + (2 * jpp + u) * 16 + brow_l, 2 * s + bkh_l)); \
                _Pragma("unroll")                                                  \
                for (int u = 0; u < 2; u++) {                                      \
                    int jp = 2 * jpp + u;                                          \
                    _Pragma("unroll")                                              \
                    for (int t = 0; t < 2; t++) {                                  \
                        mma16816h(c[t][2 * jp],     af[t], bf2[u][0], bf2[u][1]);  \
                        mma16816h(c[t][2 * jp + 1], af[t], bf2[u][2], bf2[u][3]);  \
                    }                                                              \
                }                                                                  \
            }                                                                      \
        }                                                                          \
    }

// ---------------------------------------------------------------------------
// QKV projection -> Q/K single fp16 [bh,l,d], Vt single fp16 [bh,d,l]
// ---------------------------------------------------------------------------
__global__ __launch_bounds__(256, 2)
void gemm_qkv(const float* __restrict__ bq, const float* __restrict__ bk,
              const float* __restrict__ bv)
{
    const int z = blockIdx.z;
    const float* bias = (z == 0) ? bq : (z == 1) ? bk : bv;

    GEMM_MAINLOOP(g_X, g_W + (size_t)z * DM * DM)

    const int ca = (lane & 3) * 2;
    if (z != 2) {
        __half* dst = (z == 0) ? g_Q : g_K;
        const float sc = (z == 0) ? QSCALE : 1.0f;
        #pragma unroll
        for (int t = 0; t < 2; t++) {
            int m1 = row0 + m0 + t * 16 + nrow;
            #pragma unroll
            for (int j = 0; j < 8; j++) {
                int n  = col0 + n0 + j * 8 + ca;
                int h  = n >> 6, d = n & 63;
                float b0 = bias[n], b1 = bias[n + 1];
                size_t base = ((size_t)((m1 >> 12) * NH + h) * SL + (m1 & (SL - 1))) * DKH + d;
                *(uint32_t*)(dst + base) =
                    pack_h2((c[t][j][0] + b0) * sc, (c[t][j][1] + b1) * sc);
                int m2 = m1 + 8;
                base = ((size_t)((m2 >> 12) * NH + h) * SL + (m2 & (SL - 1))) * DKH + d;
                *(uint32_t*)(dst + base) =
                    pack_h2((c[t][j][2] + b0) * sc, (c[t][j][3] + b1) * sc);
            }
        }
    } else {
        // V transposed: Vt[bh, d, l] (scalar stores, L2 merges)
        #pragma unroll
        for (int t = 0; t < 2; t++) {
            int m1 = row0 + m0 + t * 16 + nrow;
            int m2 = m1 + 8;
            int bb = m1 >> 12;
            int l1 = m1 & (SL - 1), l2 = m2 & (SL - 1);
            #pragma unroll
            for (int j = 0; j < 8; j++) {
                int n = col0 + n0 + j * 8 + ca;
                int h = n >> 6, d = n & 63;
                float b0 = bias[n], b1 = bias[n + 1];
                float v[4] = { c[t][j][0] + b0, c[t][j][1] + b1,
                               c[t][j][2] + b0, c[t][j][3] + b1 };
                int dd[4] = { d, d + 1, d, d + 1 };
                int ll[4] = { l1, l1, l2, l2 };
                #pragma unroll
                for (int u = 0; u < 4; u++) {
                    size_t base = ((size_t)(bb * NH + h) * DKH + dd[u]) * SL + ll[u];
                    g_Vt[base] = __float2half(v[u]);
                }
            }
        }
    }
}

// ---------------------------------------------------------------------------
// Output projection: out = O @ Wo^T + bo, fp32 result
// ---------------------------------------------------------------------------
__global__ __launch_bounds__(256, 2)
void gemm_out(const float* __restrict__ bias, float* __restrict__ out)
{
    GEMM_MAINLOOP(g_O, g_W + (size_t)3 * DM * DM)

    const int ca = (lane & 3) * 2;
    #pragma unroll
    for (int t = 0; t < 2; t++) {
        int m1 = row0 + m0 + t * 16 + nrow;
        #pragma unroll
        for (int j = 0; j < 8; j++) {
            int n = col0 + n0 + j * 8 + ca;
            float b0 = bias[n], b1 = bias[n + 1];
            *(float2*)(out + (size_t)m1 * DM + n) =
                make_float2(c[t][j][0] + b0, c[t][j][1] + b1);
            *(float2*)(out + (size_t)(m1 + 8) * DM + n) =
                make_float2(c[t][j][2] + b0, c[t][j][3] + b1);
        }
    }
}

// ---------------------------------------------------------------------------
// Flash attention, fp16, ldmatrix, KV tiles of 128 (2 x 64 sub-tiles).
// CTA = 128q, 8 warps: mt = wid&3 (32q), kvh = wid>>2 (32kv within sub-tile).
// Stage (32KB) = K0|K1|V0|V1 (8KB each, 64-row tiles, 128B rows, key=(r&7)<<4).
// 2 stages + Q tile (16KB at offset 65536) = 80KB; 2 CTAs/SM.
// ---------------------------------------------------------------------------
__global__ __launch_bounds__(256, 2)
void attn_kernel()
{
    extern __shared__ __align__(16) char smem[];

    const int tid  = threadIdx.x;
    const int wid  = tid >> 5;
    const int lane = tid & 31;
    const int bh   = blockIdx.y;
    const int q0   = blockIdx.x * 128;

    const int mt   = wid & 3;
    const int kvh  = wid >> 2;
    const int nrow = lane >> 2;
    const int ca   = (lane & 3) * 2;
    const int r8   = lane & 7;
    const int lg   = lane >> 3;

    const int arow_l = (lg & 1) * 8 + r8;
    const int akh_l  = lg >> 1;
    const int brow_l = (lg >> 1) * 8 + r8;
    const int bkh_l  = lg & 1;
    const uint32_t lkey = (uint32_t)(r8 << 4);

    const uint32_t sbase = smem_u32(smem);

    // --- load Q tile [128 x 64h] into smem at offset 65536 ---
    {
        const int qrow = tid >> 1;
        const int qh   = tid & 1;
        const uint32_t qkey = (uint32_t)((qrow & 7) << 4);
        const __half* Qg = g_Q + ((size_t)bh * SL + q0 + qrow) * DKH;
        uint32_t qb = sbase + 65536u + (uint32_t)(qrow * 128);
        #pragma unroll
        for (int i = 0; i < 4; i++) {
            int ch = qh * 4 + i;
            cpa16(qb + (((uint32_t)(ch * 16)) ^ qkey), Qg + ch * 8);
        }
        CPA_COMMIT();
    }

    float o[2][8][4];
    #pragma unroll
    for (int t2 = 0; t2 < 2; t2++)
        #pragma unroll
        for (int j = 0; j < 8; j++)
            #pragma unroll
            for (int e = 0; e < 4; e++) o[t2][j][e] = 0.f;
    float lsum[2][2] = {{0.f, 0.f}, {0.f, 0.f}};

    // loader: threads 0-127 fill K rows (kv 0..127 -> K0|K1);
    //         threads 128-255 (2/row) fill V rows (d 0..63, V0|V1 halves)
    const bool isK = (tid < 128);
    const int krow = tid & 127;                 // K: kv row
    const int vd   = (tid - 128) >> 1;          // V: d row
    const int vh   = tid & 1;                   // V: kv-half (V0/V1)
    const uint32_t skeyK = (uint32_t)((krow & 7) << 4);
    const uint32_t skeyV = (uint32_t)((vd & 7) << 4);
    const __half* Kg0 = g_K  + ((size_t)bh * SL + krow) * DKH;
    const __half* Vg0 = g_Vt + ((size_t)bh * DKH + vd) * SL;
    const uint32_t dK = (uint32_t)((krow & 63) * 128) + (krow >> 6) * 8192u;
    const uint32_t dV = 16384u + (uint32_t)vh * 8192u + (uint32_t)(vd * 128);

    auto issue_tile = [&](int t) {
        uint32_t sb = sbase + (uint32_t)(t & 1) * 32768u;
        int kv0 = t * 128;
        if (isK) {
            const __half* s0 = Kg0 + (size_t)kv0 * DKH;
            #pragma unroll
            for (int i = 0; i < 8; i++)
                cpa16(sb + dK + (((uint32_t)(i * 16)) ^ skeyK), s0 + i * 8);
        } else {
            const __half* s0 = Vg0 + kv0 + vh * 64;
            #pragma unroll
            for (int i = 0; i < 8; i++)
                cpa16(sb + dV + (((uint32_t)(i * 16)) ^ skeyV), s0 + i * 8);
        }
        CPA_COMMIT();
    };

    issue_tile(0);

    const uint32_t Qs = sbase + 65536u;
    const int NT = SL / 128;

    for (int t = 0; t < NT; t++) {
        CPA_WAIT0();
        __syncthreads();
        if (t + 1 < NT) issue_tile(t + 1);

        uint32_t stg = sbase + (uint32_t)(t & 1) * 32768u;

        #pragma unroll
        for (int sub = 0; sub < 2; sub++) {
            uint32_t Ks = stg + (uint32_t)sub * 8192u;
            uint32_t Vs = stg + 16384u + (uint32_t)sub * 8192u;

            // S = Q @ K^T over this warp's kv half (batched loads)
            float s[2][4][4];
            #pragma unroll
            for (int t2 = 0; t2 < 2; t2++)
                #pragma unroll
                for (int j = 0; j < 4; j++)
                    #pragma unroll
                    for (int e = 0; e < 4; e++) s[t2][j][e] = 0.f;

            #pragma unroll
            for (int kc = 0; kc < 4; kc++) {
                uint32_t af[2][4], bf[2][4];
                #pragma unroll
                for (int t2 = 0; t2 < 2; t2++) {
                    int row = mt * 32 + t2 * 16 + arow_l;
                    ldsm4(af[t2], Qs + (uint32_t)(row * 128) +
                          (((uint32_t)(kc * 32 + akh_l * 16)) ^ lkey));
                }
                #pragma unroll
                for (int jp = 0; jp < 2; jp++) {
                    int row = kvh * 32 + jp * 16 + brow_l;
                    ldsm4(bf[jp], Ks + (uint32_t)(row * 128) +
                          (((uint32_t)(kc * 32 + bkh_l * 16)) ^ lkey));
                }
                #pragma unroll
                for (int jp = 0; jp < 2; jp++)
                    #pragma unroll
                    for (int t2 = 0; t2 < 2; t2++) {
                        mma16816h(s[t2][2 * jp],     af[t2], bf[jp][0], bf[jp][1]);
                        mma16816h(s[t2][2 * jp + 1], af[t2], bf[jp][2], bf[jp][3]);
                    }
            }

            // chunked softmax + PV
            #pragma unroll
            for (int kc2 = 0; kc2 < 2; kc2++) {
                uint32_t ap[2][4];
                #pragma unroll
                for (int t2 = 0; t2 < 2; t2++) {
                    #pragma unroll
                    for (int jj = 0; jj < 2; jj++) {
                        int j = 2 * kc2 + jj;
                        s[t2][j][0] = ex2f(s[t2][j][0]); s[t2][j][1] = ex2f(s[t2][j][1]);
                        s[t2][j][2] = ex2f(s[t2][j][2]); s[t2][j][3] = ex2f(s[t2][j][3]);
                        lsum[t2][0] += s[t2][j][0] + s[t2][j][1];
                        lsum[t2][1] += s[t2][j][2] + s[t2][j][3];
                    }
                    ap[t2][0] = pack_h2(s[t2][2 * kc2][0],     s[t2][2 * kc2][1]);
                    ap[t2][1] = pack_h2(s[t2][2 * kc2][2],     s[t2][2 * kc2][3]);
                    ap[t2][2] = pack_h2(s[t2][2 * kc2 + 1][0], s[t2][2 * kc2 + 1][1]);
                    ap[t2][3] = pack_h2(s[t2][2 * kc2 + 1][2], s[t2][2 * kc2 + 1][3]);
                }
                #pragma unroll
                for (int jq = 0; jq < 2; jq++) {
                    uint32_t bv2[2][4];
                    #pragma unroll
                    for (int u = 0; u < 2; u++) {
                        int row = (2 * jq + u) * 16 + brow_l;
                        ldsm4(bv2[u], Vs + (uint32_t)(row * 128) +
                              (((uint32_t)(kvh * 64 + kc2 * 32 + bkh_l * 16)) ^ lkey));
                    }
                    #pragma unroll
                    for (int u = 0; u < 2; u++) {
                        int jdp = 2 * jq + u;
                        #pragma unroll
                        for (int t2 = 0; t2 < 2; t2++) {
                            mma16816h(o[t2][2 * jdp],     ap[t2], bv2[u][0], bv2[u][1]);
                            mma16816h(o[t2][2 * jdp + 1], ap[t2], bv2[u][2], bv2[u][3]);
                        }
                    }
                }
            }
        }
    }

    // merge kv halves
    #pragma unroll
    for (int t2 = 0; t2 < 2; t2++)
        #pragma unroll
        for (int u = 0; u < 2; u++) {
            lsum[t2][u] += __shfl_xor_sync(0xffffffffu, lsum[t2][u], 1);
            lsum[t2][u] += __shfl_xor_sync(0xffffffffu, lsum[t2][u], 2);
        }

    __syncthreads();
    float* redO = (float*)smem;              // 4 mt x 32q x 64d floats = 32KB
    float* redL = (float*)(smem + 32768);    // 128 floats

    if (kvh == 1) {
        #pragma unroll
        for (int t2 = 0; t2 < 2; t2++) {
            int r = t2 * 16 + nrow;
            #pragma unroll
            for (int jd = 0; jd < 8; jd++) {
                int col = jd * 8 + ca;
                *(float2*)&redO[mt * 2048 + r * 64 + col] =
                    make_float2(o[t2][jd][0], o[t2][jd][1]);
                *(float2*)&redO[mt * 2048 + (r + 8) * 64 + col] =
                    make_float2(o[t2][jd][2], o[t2][jd][3]);
            }
            if ((lane & 3) == 0) {
                redL[mt * 32 + t2 * 16 + nrow]     = lsum[t2][0];
                redL[mt * 32 + t2 * 16 + nrow + 8] = lsum[t2][1];
            }
        }
    }
    __syncthreads();

    if (kvh == 0) {
        const int b = bh / NH, h = bh % NH;
        #pragma unroll
        for (int t2 = 0; t2 < 2; t2++) {
            int r = t2 * 16 + nrow;
            float lt0 = lsum[t2][0] + redL[mt * 32 + r];
            float lt1 = lsum[t2][1] + redL[mt * 32 + r + 8];
            float inv0 = 1.f / lt0, inv1 = 1.f / lt1;
            int row = q0 + mt * 32 + r;
            size_t base0 = ((size_t)b * SL + row) * DM + h * DKH;
            size_t base1 = base0 + (size_t)8 * DM;
            #pragma unroll
            for (int jd = 0; jd < 8; jd++) {
                int col = jd * 8 + ca;
                float2 p0 = *(float2*)&redO[mt * 2048 + r * 64 + col];
                float2 p1 = *(float2*)&redO[mt * 2048 + (r + 8) * 64 + col];
                *(uint32_t*)(g_O + base0 + col) =
                    pack_h2((o[t2][jd][0] + p0.x) * inv0, (o[t2][jd][1] + p0.y) * inv0);
                *(uint32_t*)(g_O + base1 + col) =
                    pack_h2((o[t2][jd][2] + p1.x) * inv1, (o[t2][jd][3] + p1.y) * inv1);
            }
        }
    }
}

// ---------------------------------------------------------------------------
extern "C" void kernel_launch(void* const* d_in, const int* in_sizes, int n_in,
                              void* d_out, int out_size)
{
    (void)in_sizes; (void)n_in; (void)out_size;
    const float* x  = (const float*)d_in[0];
    const float* Wq = (const float*)d_in[1];
    const float* bq = (const float*)d_in[2];
    const float* Wk = (const float*)d_in[3];
    const float* bk = (const float*)d_in[4];
    const float* Wv = (const float*)d_in[5];
    const float* bv = (const float*)d_in[6];
    const float* Wo = (const float*)d_in[7];
    const float* bo = (const float*)d_in[8];
    float* out = (float*)d_out;

    cudaFuncSetAttribute(gemm_qkv, cudaFuncAttributeMaxDynamicSharedMemorySize, GEMM_SMEM);
    cudaFuncSetAttribute(gemm_out, cudaFuncAttributeMaxDynamicSharedMemorySize, GEMM_SMEM);
    cudaFuncSetAttribute(attn_kernel, cudaFuncAttributeMaxDynamicSharedMemorySize, ATT_SMEM);

    dim3 gs(12288, 5);
    split_kernel<<<gs, 256>>>(x, Wq, Wk, Wv, Wo);

    dim3 gq(DM / 128, MT / 128, 3);
    gemm_qkv<<<gq, 256, GEMM_SMEM>>>(bq, bk, bv);

    dim3 ga(SL / 128, NBH);
    attn_kernel<<<ga, 256, ATT_SMEM>>>();

    dim3 go(DM / 128, MT / 128);
    gemm_out<<<go, 256, GEMM_SMEM>>>(bo, out);
}